// round 6
// baseline (speedup 1.0000x reference)
#include <cuda_runtime.h>
#include <math.h>

#define NSTACK 4
#define BATCH  4
#define LSEQ   600
#define DMODEL 36
#define DFF    144
#define QT     30      // queries per attention block
#define NTILES 20      // 600 / QT
#define NI     19      // ceil(600/32)

// ---------------- scratch (device globals; no allocation) ----------------
__device__ float g_z[NSTACK*BATCH*LSEQ*DMODEL];   // residual stream per stack
__device__ float g_q[NSTACK*BATCH*LSEQ*DMODEL];
__device__ float g_k[NSTACK*BATCH*LSEQ*DMODEL];
__device__ float g_v[NSTACK*BATCH*LSEQ*DMODEL];
__device__ float g_o[NSTACK*BATCH*LSEQ*DMODEL];
__device__ float g_g[NSTACK*BATCH*LSEQ*DFF];      // gelu(ffn1) activations
__device__ float g_gate[NSTACK*BATCH*DMODEL];     // SE gates

// ---------------- helpers ----------------
__device__ __forceinline__ int pick4(int4 v, int s) {
    return (s == 0) ? v.x : (s == 1) ? v.y : (s == 2) ? v.z : v.w;
}

__device__ __forceinline__ void ln_stats(const float* v36, float* ms) {
    float m = 0.f;
#pragma unroll
    for (int d = 0; d < 36; d++) m += v36[d];
    m *= (1.f / 36.f);
    float var = 0.f;
#pragma unroll
    for (int d = 0; d < 36; d++) { float c = v36[d] - m; var += c * c; }
    var *= (1.f / 36.f);
    ms[0] = m;
    ms[1] = rsqrtf(var + 1e-6f);
}

__device__ __forceinline__ void do_qkv(
    int t, int r, int L, const float* ysh,
    const float* __restrict__ Wq, const float* __restrict__ bq,
    const float* __restrict__ Wk, const float* __restrict__ bk,
    const float* __restrict__ Wv, const float* __restrict__ bv)
{
    if (t < 108) {
        int which = t / 36, j = t % 36;
        const float* W; const float* bb; float* out;
        if (which == 0)      { W = Wq; bb = bq; out = g_q; }
        else if (which == 1) { W = Wk; bb = bk; out = g_k; }
        else                 { W = Wv; bb = bv; out = g_v; }
        W += L * 1296;
        float acc = bb[L * 36 + j];
#pragma unroll
        for (int d = 0; d < 36; d++) acc += ysh[d] * W[d * 36 + j];
        out[r * 36 + j] = acc;
    }
}

// ---------------- embedding: x transpose + sinusoidal PE ----------------
__global__ void embed_kernel(const float* __restrict__ x)
{
    int idx = blockIdx.x * blockDim.x + threadIdx.x;
    if (idx >= NSTACK * BATCH * LSEQ * DMODEL) return;
    int d = idx % 36;
    int l = (idx / 36) % 600;
    int b = (idx / 21600) % 4;
    int j = d >> 1;
    float freq = __expf(-logf(10000.f) * (float)(2 * j) / 36.f);
    float ang = (float)l * freq;
    float pe = (d & 1) ? cosf(ang) : sinf(ang);
    g_z[idx] = x[b * 21600 + d * 600 + l] + pe;
}

// ---------------- LN1 + QKV (initial) ----------------
__global__ void __launch_bounds__(128) lnqkv_kernel(
    int4 layer4,
    const float* __restrict__ ln1_g, const float* __restrict__ ln1_b,
    const float* __restrict__ Wq, const float* __restrict__ bq,
    const float* __restrict__ Wk, const float* __restrict__ bk,
    const float* __restrict__ Wv, const float* __restrict__ bv)
{
    int l = blockIdx.x, b = blockIdx.y, s = blockIdx.z;
    int L = pick4(layer4, s);
    int r = (s * 4 + b) * 600 + l;
    __shared__ float zsh[36], ysh[36], ms[2];
    int t = threadIdx.x;
    if (t < 36) zsh[t] = g_z[r * 36 + t];
    __syncthreads();
    if (t == 0) ln_stats(zsh, ms);
    __syncthreads();
    if (t < 36) ysh[t] = ln1_g[L * 36 + t] * (zsh[t] - ms[0]) * ms[1] + ln1_b[L * 36 + t];
    __syncthreads();
    do_qkv(t, r, L, ysh, Wq, bq, Wk, bk, Wv, bv);
}

// ---------------- attention: full K/V in smem, register-blocked heads ----------------
template<int DK, int NQ>
__device__ __forceinline__ void attn_head_group(
    const float* __restrict__ ksh, const float* __restrict__ vsh,
    const float* __restrict__ qsh, float* __restrict__ ob,
    int q0, int g, int off, int lane)
{
    float qreg[NQ][DK];
#pragma unroll
    for (int qq = 0; qq < NQ; qq++) {
        int ql = g * NQ + qq;
#pragma unroll
        for (int d = 0; d < DK; d++)
            qreg[qq][d] = (ql < QT) ? qsh[ql * 36 + off + d] : 0.f;
    }
    float sc[NQ][NI];
#pragma unroll
    for (int qq = 0; qq < NQ; qq++)
#pragma unroll
        for (int i = 0; i < NI; i++) sc[qq][i] = 0.f;

#pragma unroll
    for (int i = 0; i < NI; i++) {
        int m = i * 32 + lane;
        if (m < LSEQ) {
            const float* kr = ksh + m * 36 + off;
#pragma unroll
            for (int d = 0; d < DK; d++) {
                float kv = kr[d];
#pragma unroll
                for (int qq = 0; qq < NQ; qq++)
                    sc[qq][i] = fmaf(qreg[qq][d], kv, sc[qq][i]);
            }
        } else {
#pragma unroll
            for (int qq = 0; qq < NQ; qq++) sc[qq][i] = -1e30f;
        }
    }
    const float scale = rsqrtf((float)DK);
    float inv[NQ];
#pragma unroll
    for (int qq = 0; qq < NQ; qq++) {
        float mx = -1e30f;
#pragma unroll
        for (int i = 0; i < NI; i++) { float v = sc[qq][i] * scale; sc[qq][i] = v; mx = fmaxf(mx, v); }
#pragma unroll
        for (int o = 16; o > 0; o >>= 1) mx = fmaxf(mx, __shfl_xor_sync(0xffffffffu, mx, o));
        float sm = 0.f;
#pragma unroll
        for (int i = 0; i < NI; i++) { float p = __expf(sc[qq][i] - mx); sc[qq][i] = p; sm += p; }
#pragma unroll
        for (int o = 16; o > 0; o >>= 1) sm += __shfl_xor_sync(0xffffffffu, sm, o);
        inv[qq] = 1.f / sm;
    }
    float acc[NQ][DK];
#pragma unroll
    for (int qq = 0; qq < NQ; qq++)
#pragma unroll
        for (int d = 0; d < DK; d++) acc[qq][d] = 0.f;

#pragma unroll
    for (int i = 0; i < NI; i++) {
        int m = i * 32 + lane;
        if (m < LSEQ) {
            const float* vr = vsh + m * 36 + off;
#pragma unroll
            for (int d = 0; d < DK; d++) {
                float vv = vr[d];
#pragma unroll
                for (int qq = 0; qq < NQ; qq++)
                    acc[qq][d] = fmaf(sc[qq][i], vv, acc[qq][d]);
            }
        }
    }
#pragma unroll
    for (int qq = 0; qq < NQ; qq++) {
        int ql = g * NQ + qq;
#pragma unroll
        for (int d = 0; d < DK; d++) {
            float a = acc[qq][d];
#pragma unroll
            for (int o = 16; o > 0; o >>= 1) a += __shfl_xor_sync(0xffffffffu, a, o);
            if (ql < QT && lane == ((qq * DK + d) & 31))
                ob[(q0 + ql) * 36 + off + d] = a * inv[qq];
        }
    }
}

template<int DK, int NQ>
__device__ void attn_run(const float* ksh, const float* vsh, const float* qsh,
                         float* ob, int q0, int lane, int wid)
{
    constexpr int H  = 36 / DK;
    constexpr int NG = (QT + NQ - 1) / NQ;
    for (int hh = 0; hh < H; hh++) {
        int off = hh * DK;
        for (int g = wid; g < NG; g += 8)
            attn_head_group<DK, NQ>(ksh, vsh, qsh, ob, q0, g, off, lane);
    }
}

__global__ void __launch_bounds__(256, 1) attn_kernel(int4 heads4)
{
    extern __shared__ float sh[];
    float* ksh = sh;
    float* vsh = sh + 21600;
    float* qsh = sh + 43200;
    int tile = blockIdx.x, b = blockIdx.y, s = blockIdx.z;
    int h = pick4(heads4, s);
    int base = (s * 4 + b) * 21600;

    const float4* kg = (const float4*)(g_k + base);
    const float4* vg = (const float4*)(g_v + base);
    float4* k4 = (float4*)ksh;
    float4* v4 = (float4*)vsh;
    for (int i = threadIdx.x; i < 5400; i += 256) { k4[i] = kg[i]; v4[i] = vg[i]; }
    int q0 = tile * QT;
    for (int i = threadIdx.x; i < QT * 36; i += 256) qsh[i] = g_q[base + q0 * 36 + i];
    __syncthreads();

    int lane = threadIdx.x & 31, wid = threadIdx.x >> 5;
    float* ob = g_o + base;
    switch (h) {
        case 1:  attn_run<36, 2>(ksh, vsh, qsh, ob, q0, lane, wid); break;
        case 2:  attn_run<18, 2>(ksh, vsh, qsh, ob, q0, lane, wid); break;
        case 3:  attn_run<12, 3>(ksh, vsh, qsh, ob, q0, lane, wid); break;
        case 4:  attn_run<9,  4>(ksh, vsh, qsh, ob, q0, lane, wid); break;
        case 6:  attn_run<6,  4>(ksh, vsh, qsh, ob, q0, lane, wid); break;
        case 9:  attn_run<4,  4>(ksh, vsh, qsh, ob, q0, lane, wid); break;
        case 12: attn_run<3,  4>(ksh, vsh, qsh, ob, q0, lane, wid); break;
        case 18: attn_run<2,  4>(ksh, vsh, qsh, ob, q0, lane, wid); break;
        case 36: attn_run<1,  4>(ksh, vsh, qsh, ob, q0, lane, wid); break;
    }
}

// ---------------- O-proj + residual + LN2 + FFN1 + GELU ----------------
__global__ void __launch_bounds__(160) oproj_ffn1_kernel(
    int4 layer4,
    const float* __restrict__ Wo, const float* __restrict__ bo,
    const float* __restrict__ ln2_g, const float* __restrict__ ln2_b,
    const float* __restrict__ W1, const float* __restrict__ b1)
{
    int l = blockIdx.x, b = blockIdx.y, s = blockIdx.z;
    int L = pick4(layer4, s);
    int r = (s * 4 + b) * 600 + l;
    __shared__ float osh[36], zsh[36], tsh[36], ysh[36], ms[2];
    int t = threadIdx.x;
    if (t < 36) { osh[t] = g_o[r * 36 + t]; zsh[t] = g_z[r * 36 + t]; }
    __syncthreads();
    if (t < 36) {
        float acc = bo[L * 36 + t];
        const float* W = Wo + L * 1296;
#pragma unroll
        for (int d = 0; d < 36; d++) acc += osh[d] * W[d * 36 + t];
        float tv = acc + zsh[t];
        tsh[t] = tv;
        g_z[r * 36 + t] = tv;           // z2 (post-attention residual)
    }
    __syncthreads();
    if (t == 0) ln_stats(tsh, ms);
    __syncthreads();
    if (t < 36) ysh[t] = ln2_g[L * 36 + t] * (tsh[t] - ms[0]) * ms[1] + ln2_b[L * 36 + t];
    __syncthreads();
    if (t < 144) {
        float acc = b1[L * 144 + t];
        const float* W = W1 + L * 5184;
#pragma unroll
        for (int d = 0; d < 36; d++) acc += ysh[d] * W[d * 144 + t];
        float u = acc;
        float th = tanhf(0.7978845608028654f * (u + 0.044715f * u * u * u));
        g_g[r * 144 + t] = 0.5f * u * (1.f + th);
    }
}

// ---------------- FFN2 + residual, fused with NEXT layer's LN1+QKV ----------------
__global__ void __launch_bounds__(160) ffn2_lnqkv_kernel(
    int4 layer4, int4 next4,
    const float* __restrict__ W2, const float* __restrict__ b2,
    const float* __restrict__ ln1_g, const float* __restrict__ ln1_b,
    const float* __restrict__ Wq, const float* __restrict__ bq,
    const float* __restrict__ Wk, const float* __restrict__ bk,
    const float* __restrict__ Wv, const float* __restrict__ bv)
{
    int l = blockIdx.x, b = blockIdx.y, s = blockIdx.z;
    int L  = pick4(layer4, s);
    int Ln = pick4(next4, s);
    int r = (s * 4 + b) * 600 + l;
    __shared__ float gsh[144], zsh[36], znsh[36], ysh[36], ms[2];
    int t = threadIdx.x;
    if (t < 144) gsh[t] = g_g[r * 144 + t];
    if (t < 36)  zsh[t] = g_z[r * 36 + t];
    __syncthreads();
    if (t < 36) {
        float acc = b2[L * 36 + t];
        const float* W = W2 + L * 5184;
#pragma unroll 8
        for (int d = 0; d < 144; d++) acc += gsh[d] * W[d * 36 + t];
        float zn = acc + zsh[t];
        znsh[t] = zn;
        g_z[r * 36 + t] = zn;           // new residual stream / branch output
    }
    __syncthreads();
    if (Ln < 0) return;                 // uniform per block
    if (t == 0) ln_stats(znsh, ms);
    __syncthreads();
    if (t < 36) ysh[t] = ln1_g[Ln * 36 + t] * (znsh[t] - ms[0]) * ms[1] + ln1_b[Ln * 36 + t];
    __syncthreads();
    do_qkv(t, r, Ln, ysh, Wq, bq, Wk, bk, Wv, bv);
}

// ---------------- SE gate: sigmoid(mean over L) ----------------
__global__ void __launch_bounds__(288) gate_kernel()
{
    int sb = blockIdx.x;  // 0..15 = s*4+b
    __shared__ float red[288];
    int t = threadIdx.x;
    int c = t / 8, k = t % 8;
    float sum = 0.f;
    const float* zz = g_z + sb * 21600;
    for (int l = k; l < 600; l += 8) sum += zz[l * 36 + c];
    red[t] = sum;
    __syncthreads();
    if (k == 0) {
        float tot = 0.f;
#pragma unroll
        for (int i = 0; i < 8; i++) tot += red[c * 8 + i];
        float mean = tot * (1.f / 600.f);
        g_gate[sb * 36 + c] = 1.f / (1.f + __expf(-mean));
    }
}

// ---------------- gated concat + conv1d(k=3) + BN + ReLU ----------------
__global__ void __launch_bounds__(360) conv_kernel(
    const float* __restrict__ conv_w, const float* __restrict__ conv_b,
    const float* __restrict__ bn_g, const float* __restrict__ bn_b,
    const float* __restrict__ bn_mean, const float* __restrict__ bn_var,
    float* __restrict__ out)
{
    extern __shared__ float esh[];
    float* xf  = esh;              // [144][32]
    float* wsh = esh + 144 * 32;   // [36][433] padded rows (conflict-free)
    int b = blockIdx.y, lbase = blockIdx.x * 30;
    int t = threadIdx.x;

    for (int idx = t; idx < 144 * 32; idx += 360) {
        int i = idx >> 5, lc = idx & 31;
        int l = lbase + lc - 1;
        float val = 0.f;
        if (l >= 0 && l < 600) {
            int s = i / 36, c = i % 36;
            val = g_gate[(s * 4 + b) * 36 + c] * g_z[((s * 4 + b) * 600 + l) * 36 + c];
        }
        xf[i * 32 + lc] = val;
    }
    for (int idx = t; idx < 36 * 432; idx += 360) {
        int o = idx / 432, rest = idx % 432;
        wsh[o * 433 + rest] = conv_w[idx];
    }
    __syncthreads();

    int o = t % 36, lj = t / 36;   // lj in [0,10)
    float scale = bn_g[o] * rsqrtf(bn_var[o] + 1e-5f);
    float shift = bn_b[o] - scale * bn_mean[o];
    float cb = conv_b[o];
    const float* w = wsh + o * 433;
#pragma unroll
    for (int rep = 0; rep < 3; rep++) {
        int lc = lj + rep * 10;
        float acc = cb;
#pragma unroll 8
        for (int i = 0; i < 144; i++) {
            float x0 = xf[i * 32 + lc];
            float x1 = xf[i * 32 + lc + 1];
            float x2 = xf[i * 32 + lc + 2];
            acc += x0 * w[i * 3 + 0] + x1 * w[i * 3 + 1] + x2 * w[i * 3 + 2];
        }
        float y = scale * acc + shift;
        out[b * 21600 + o * 600 + lbase + lc] = fmaxf(y, 0.f);
    }
}

// ---------------- host driver ----------------
extern "C" void kernel_launch(void* const* d_in, const int* in_sizes, int n_in,
                              void* d_out, int out_size)
{
    (void)in_sizes; (void)n_in; (void)out_size;
    const float* x     = (const float*)d_in[0];
    const float* ln1_g = (const float*)d_in[1];
    const float* ln1_b = (const float*)d_in[2];
    const float* Wq    = (const float*)d_in[3];
    const float* bq    = (const float*)d_in[4];
    const float* Wk    = (const float*)d_in[5];
    const float* bk    = (const float*)d_in[6];
    const float* Wv    = (const float*)d_in[7];
    const float* bv    = (const float*)d_in[8];
    const float* Wo    = (const float*)d_in[9];
    const float* bo    = (const float*)d_in[10];
    const float* ln2_g = (const float*)d_in[11];
    const float* ln2_b = (const float*)d_in[12];
    const float* W1    = (const float*)d_in[13];
    const float* b1    = (const float*)d_in[14];
    const float* W2    = (const float*)d_in[15];
    const float* b2    = (const float*)d_in[16];
    const float* conv_w = (const float*)d_in[17];
    const float* conv_b = (const float*)d_in[18];
    const float* bn_g   = (const float*)d_in[19];
    const float* bn_b   = (const float*)d_in[20];
    const float* bn_mean = (const float*)d_in[21];
    const float* bn_var  = (const float*)d_in[22];
    float* out = (float*)d_out;

    static const int HEADS_H[24] = {1,2,3,4,6,9,12,18,36,
                                    1,2,3,4,6,
                                    6,9,12,18,36,
                                    3,4,6,9,12};
    static const int START[4] = {0, 9, 14, 19};
    static const int DEPTH[4] = {9, 5, 5, 5};

    const int ATTN_SMEM = (21600 * 2 + QT * 36) * 4;          // 177120 B
    const int CONV_SMEM = (144 * 32 + 36 * 433) * 4;          // 80784 B
    cudaFuncSetAttribute(attn_kernel, cudaFuncAttributeMaxDynamicSharedMemorySize, ATTN_SMEM);
    cudaFuncSetAttribute(conv_kernel, cudaFuncAttributeMaxDynamicSharedMemorySize, CONV_SMEM);

    embed_kernel<<<1350, 256>>>(x);

    int4 L0 = make_int4(0, 9, 14, 19);
    lnqkv_kernel<<<dim3(600, 4, 4), 128>>>(L0, ln1_g, ln1_b, Wq, bq, Wk, bk, Wv, bv);

    for (int t = 0; t < 9; t++) {
        int nA = (t < 5) ? 4 : 1;
        int lc[4], nx[4], hh[4];
        for (int s = 0; s < 4; s++) {
            int L = START[s] + t;
            lc[s] = (L < 24) ? L : 0;
            hh[s] = (t < DEPTH[s]) ? HEADS_H[lc[s]] : 1;
            nx[s] = (t + 1 < DEPTH[s]) ? lc[s] + 1 : -1;
        }
        int4 Lc = make_int4(lc[0], lc[1], lc[2], lc[3]);
        int4 Nx = make_int4(nx[0], nx[1], nx[2], nx[3]);
        int4 Hh = make_int4(hh[0], hh[1], hh[2], hh[3]);

        attn_kernel<<<dim3(NTILES, 4, nA), 256, ATTN_SMEM>>>(Hh);
        oproj_ffn1_kernel<<<dim3(600, 4, nA), 160>>>(Lc, Wo, bo, ln2_g, ln2_b, W1, b1);
        ffn2_lnqkv_kernel<<<dim3(600, 4, nA), 160>>>(Lc, Nx, W2, b2,
                                                     ln1_g, ln1_b, Wq, bq, Wk, bk, Wv, bv);
    }

    gate_kernel<<<16, 288>>>();
    conv_kernel<<<dim3(20, 4), 360, CONV_SMEM>>>(conv_w, conv_b, bn_g, bn_b,
                                                 bn_mean, bn_var, out);
}

// round 7
// speedup vs baseline: 1.1341x; 1.1341x over previous
#include <cuda_runtime.h>
#include <math.h>

#define NSTACK 4
#define BATCH  4
#define LSEQ   600
#define DMODEL 36
#define DFF    144
#define QT     30
#define NTILES 20
#define NI     19

// ---------------- scratch ----------------
__device__ float g_z[NSTACK*BATCH*LSEQ*DMODEL];
__device__ float g_q[NSTACK*BATCH*LSEQ*DMODEL];
__device__ float g_k[NSTACK*BATCH*LSEQ*DMODEL];
__device__ float g_v[NSTACK*BATCH*LSEQ*DMODEL];
__device__ float g_o[NSTACK*BATCH*LSEQ*DMODEL];
__device__ float g_gate[NSTACK*BATCH*DMODEL];

__device__ __forceinline__ int pick4(int4 v, int s) {
    return (s == 0) ? v.x : (s == 1) ? v.y : (s == 2) ? v.z : v.w;
}
__device__ __forceinline__ float wred(float v) {
#pragma unroll
    for (int o = 16; o > 0; o >>= 1) v += __shfl_xor_sync(0xffffffffu, v, o);
    return v;
}
__device__ __forceinline__ float gelu(float u) {
    float th = tanhf(0.7978845608028654f * (u + 0.044715f * u * u * u));
    return 0.5f * u * (1.f + th);
}
// cooperative copy, n divisible by 4, 16B-aligned src/dst
__device__ __forceinline__ void cp4(float* dst, const float* __restrict__ src,
                                    int n, int tid, int nt) {
    const float4* s4 = (const float4*)src;
    float4* d4 = (float4*)dst;
    for (int i = tid; i < (n >> 2); i += nt) d4[i] = s4[i];
}

// ---------------- embedding ----------------
__global__ void embed_kernel(const float* __restrict__ x)
{
    int idx = blockIdx.x * blockDim.x + threadIdx.x;
    if (idx >= NSTACK * BATCH * LSEQ * DMODEL) return;
    int d = idx % 36;
    int l = (idx / 36) % 600;
    int b = (idx / 21600) % 4;
    int j = d >> 1;
    float freq = __expf(-logf(10000.f) * (float)(2 * j) / 36.f);
    float ang = (float)l * freq;
    float pe = (d & 1) ? cosf(ang) : sinf(ang);
    g_z[idx] = x[b * 21600 + d * 600 + l] + pe;
}

// =============================================================
// Initial LN1 + QKV, tiled: 256 threads, 8 warps, 2 rows/warp
// smem: Wq/Wk/Wv(3x1296) + ln1g/b, bq/bk/bv + ybuf(16x40)
// =============================================================
#define LQ_WQ 0
#define LQ_WK 1296
#define LQ_WV 2592
#define LQ_LG 3888
#define LQ_LB 3924
#define LQ_BQ 3960
#define LQ_BK 3996
#define LQ_BV 4032
#define LQ_YB 4068
#define LQ_TOT (4068 + 16*40)

__global__ void __launch_bounds__(256, 2) lnqkv2_kernel(
    int4 layer4,
    const float* __restrict__ ln1_g, const float* __restrict__ ln1_b,
    const float* __restrict__ Wq, const float* __restrict__ bq,
    const float* __restrict__ Wk, const float* __restrict__ bk,
    const float* __restrict__ Wv, const float* __restrict__ bv)
{
    extern __shared__ float sm[];
    int tid = threadIdx.x, lane = tid & 31, w = tid >> 5;
    int s = blockIdx.z;
    int L = pick4(layer4, s);

    cp4(sm + LQ_WQ, Wq + L * 1296, 1296, tid, 256);
    cp4(sm + LQ_WK, Wk + L * 1296, 1296, tid, 256);
    cp4(sm + LQ_WV, Wv + L * 1296, 1296, tid, 256);
    cp4(sm + LQ_LG, ln1_g + L * 36, 36, tid, 256);
    cp4(sm + LQ_LB, ln1_b + L * 36, 36, tid, 256);
    cp4(sm + LQ_BQ, bq + L * 36, 36, tid, 256);
    cp4(sm + LQ_BK, bk + L * 36, 36, tid, 256);
    cp4(sm + LQ_BV, bv + L * 36, 36, tid, 256);
    __syncthreads();

    int rA = blockIdx.x * 16 + w * 2;
    int gA = s * 2400 + rA, gB = gA + 1;
    int j = lane, j2 = lane + 32;
    bool e2 = lane < 4;
    float* bufA = sm + LQ_YB + (w * 2) * 40;
    float* bufB = bufA + 40;

    // stage z rows
    bufA[lane] = g_z[gA * 36 + lane];
    bufB[lane] = g_z[gB * 36 + lane];
    if (e2) { bufA[j2] = g_z[gA * 36 + j2]; bufB[j2] = g_z[gB * 36 + j2]; }
    __syncwarp();

    float tA0 = bufA[j], tB0 = bufB[j];
    float tA1 = e2 ? bufA[j2] : 0.f, tB1 = e2 ? bufB[j2] : 0.f;
    float sA = wred(tA0 + (e2 ? tA1 : 0.f));
    float qA = wred(tA0 * tA0 + (e2 ? tA1 * tA1 : 0.f));
    float sB = wred(tB0 + (e2 ? tB1 : 0.f));
    float qB = wred(tB0 * tB0 + (e2 ? tB1 * tB1 : 0.f));
    float mA = sA * (1.f / 36.f), mB = sB * (1.f / 36.f);
    float rsA = rsqrtf(qA * (1.f / 36.f) - mA * mA + 1e-6f);
    float rsB = rsqrtf(qB * (1.f / 36.f) - mB * mB + 1e-6f);

    bufA[j] = sm[LQ_LG + j] * (tA0 - mA) * rsA + sm[LQ_LB + j];
    bufB[j] = sm[LQ_LG + j] * (tB0 - mB) * rsB + sm[LQ_LB + j];
    if (e2) {
        bufA[j2] = sm[LQ_LG + j2] * (tA1 - mA) * rsA + sm[LQ_LB + j2];
        bufB[j2] = sm[LQ_LG + j2] * (tB1 - mB) * rsB + sm[LQ_LB + j2];
    }
    __syncwarp();

    float aA[36], aB[36];
#pragma unroll
    for (int d = 0; d < 36; d++) { aA[d] = bufA[d]; aB[d] = bufB[d]; }

    const int WOFF[3] = {LQ_WQ, LQ_WK, LQ_WV};
    const int BOFF[3] = {LQ_BQ, LQ_BK, LQ_BV};
    float* OUT[3] = {g_q, g_k, g_v};
#pragma unroll
    for (int m = 0; m < 3; m++) {
        const float* Ws = sm + WOFF[m];
        const float* bs = sm + BOFF[m];
        float cA0 = bs[j], cB0 = bs[j];
        float cA1 = 0.f, cB1 = 0.f;
        if (e2) { cA1 = bs[j2]; cB1 = bs[j2]; }
#pragma unroll
        for (int d = 0; d < 36; d++) {
            float wv = Ws[d * 36 + j];
            cA0 = fmaf(aA[d], wv, cA0);
            cB0 = fmaf(aB[d], wv, cB0);
            if (e2) {
                float wv2 = Ws[d * 36 + j2];
                cA1 = fmaf(aA[d], wv2, cA1);
                cB1 = fmaf(aB[d], wv2, cB1);
            }
        }
        OUT[m][gA * 36 + j] = cA0;
        OUT[m][gB * 36 + j] = cB0;
        if (e2) { OUT[m][gA * 36 + j2] = cA1; OUT[m][gB * 36 + j2] = cB1; }
    }
}

// =============================================================
// Fused row chain: o-proj+res -> LN2 -> FFN1+GELU -> FFN2+res
//                  -> (next) LN1 -> QKV
// 256 threads = 8 warps = 16 rows (2 rows per warp)
// =============================================================
#define RC_WO   0
#define RC_W1   1296
#define RC_W2   6480
#define RC_WQ   11664
#define RC_WK   12960
#define RC_WV   14256
#define RC_BO   15552
#define RC_L2G  15588
#define RC_L2B  15624
#define RC_B2   15660
#define RC_B1   15696
#define RC_L1G  15840
#define RC_L1B  15876
#define RC_BQ   15912
#define RC_BK   15948
#define RC_BV   15984
#define RC_YB   16020
#define RC_GB   (16020 + 16*40)
#define RC_TOT  (RC_GB + 16*144)

__global__ void __launch_bounds__(256, 2) rowchain_kernel(
    int4 layer4, int4 next4,
    const float* __restrict__ Wo, const float* __restrict__ bo,
    const float* __restrict__ ln2_g, const float* __restrict__ ln2_b,
    const float* __restrict__ W1, const float* __restrict__ b1,
    const float* __restrict__ W2, const float* __restrict__ b2,
    const float* __restrict__ ln1_g, const float* __restrict__ ln1_b,
    const float* __restrict__ Wq, const float* __restrict__ bq,
    const float* __restrict__ Wk, const float* __restrict__ bk,
    const float* __restrict__ Wv, const float* __restrict__ bv)
{
    extern __shared__ float sm[];
    int tid = threadIdx.x, lane = tid & 31, w = tid >> 5;
    int s = blockIdx.z;
    int L = pick4(layer4, s);
    int Ln = pick4(next4, s);

    cp4(sm + RC_WO, Wo + L * 1296, 1296, tid, 256);
    cp4(sm + RC_W1, W1 + L * 5184, 5184, tid, 256);
    cp4(sm + RC_W2, W2 + L * 5184, 5184, tid, 256);
    cp4(sm + RC_BO, bo + L * 36, 36, tid, 256);
    cp4(sm + RC_L2G, ln2_g + L * 36, 36, tid, 256);
    cp4(sm + RC_L2B, ln2_b + L * 36, 36, tid, 256);
    cp4(sm + RC_B2, b2 + L * 36, 36, tid, 256);
    cp4(sm + RC_B1, b1 + L * 144, 144, tid, 256);
    if (Ln >= 0) {
        cp4(sm + RC_WQ, Wq + Ln * 1296, 1296, tid, 256);
        cp4(sm + RC_WK, Wk + Ln * 1296, 1296, tid, 256);
        cp4(sm + RC_WV, Wv + Ln * 1296, 1296, tid, 256);
        cp4(sm + RC_L1G, ln1_g + Ln * 36, 36, tid, 256);
        cp4(sm + RC_L1B, ln1_b + Ln * 36, 36, tid, 256);
        cp4(sm + RC_BQ, bq + Ln * 36, 36, tid, 256);
        cp4(sm + RC_BK, bk + Ln * 36, 36, tid, 256);
        cp4(sm + RC_BV, bv + Ln * 36, 36, tid, 256);
    }
    __syncthreads();

    int rA = blockIdx.x * 16 + w * 2;
    int gA = s * 2400 + rA, gB = gA + 1;
    int j = lane, j2 = lane + 32;
    bool e2 = lane < 4;
    float* bufA = sm + RC_YB + (w * 2) * 40;
    float* bufB = bufA + 40;
    float* gbA  = sm + RC_GB + (w * 2) * 144;
    float* gbB  = gbA + 144;

    // ---- stage attention output rows ----
    bufA[lane] = g_o[gA * 36 + lane];
    bufB[lane] = g_o[gB * 36 + lane];
    if (e2) { bufA[j2] = g_o[gA * 36 + j2]; bufB[j2] = g_o[gB * 36 + j2]; }
    __syncwarp();

    float aA[36], aB[36];
#pragma unroll
    for (int d = 0; d < 36; d++) { aA[d] = bufA[d]; aB[d] = bufB[d]; }

    float zA0 = g_z[gA * 36 + j], zB0 = g_z[gB * 36 + j];
    float zA1 = e2 ? g_z[gA * 36 + j2] : 0.f;
    float zB1 = e2 ? g_z[gB * 36 + j2] : 0.f;

    // ---- o-projection + residual ----
    float tA0 = sm[RC_BO + j], tB0 = sm[RC_BO + j];
    float tA1 = 0.f, tB1 = 0.f;
    if (e2) { tA1 = sm[RC_BO + j2]; tB1 = sm[RC_BO + j2]; }
#pragma unroll
    for (int d = 0; d < 36; d++) {
        float wv = sm[RC_WO + d * 36 + j];
        tA0 = fmaf(aA[d], wv, tA0);
        tB0 = fmaf(aB[d], wv, tB0);
        if (e2) {
            float wv2 = sm[RC_WO + d * 36 + j2];
            tA1 = fmaf(aA[d], wv2, tA1);
            tB1 = fmaf(aB[d], wv2, tB1);
        }
    }
    tA0 += zA0; tB0 += zB0; tA1 += zA1; tB1 += zB1;

    // ---- LN2 (warp shuffles) ----
    {
        float sA = wred(tA0 + (e2 ? tA1 : 0.f));
        float qA = wred(tA0 * tA0 + (e2 ? tA1 * tA1 : 0.f));
        float sB = wred(tB0 + (e2 ? tB1 : 0.f));
        float qB = wred(tB0 * tB0 + (e2 ? tB1 * tB1 : 0.f));
        float mA = sA * (1.f / 36.f), mB = sB * (1.f / 36.f);
        float rsA = rsqrtf(qA * (1.f / 36.f) - mA * mA + 1e-6f);
        float rsB = rsqrtf(qB * (1.f / 36.f) - mB * mB + 1e-6f);
        bufA[j] = sm[RC_L2G + j] * (tA0 - mA) * rsA + sm[RC_L2B + j];
        bufB[j] = sm[RC_L2G + j] * (tB0 - mB) * rsB + sm[RC_L2B + j];
        if (e2) {
            bufA[j2] = sm[RC_L2G + j2] * (tA1 - mA) * rsA + sm[RC_L2B + j2];
            bufB[j2] = sm[RC_L2G + j2] * (tB1 - mB) * rsB + sm[RC_L2B + j2];
        }
    }
    __syncwarp();
#pragma unroll
    for (int d = 0; d < 36; d++) { aA[d] = bufA[d]; aB[d] = bufB[d]; }

    // ---- FFN1 + GELU ----
    {
        float fA[4], fB[4];
#pragma unroll
        for (int k = 0; k < 4; k++) {
            fA[k] = sm[RC_B1 + lane + 32 * k];
            fB[k] = fA[k];
        }
#pragma unroll
        for (int d = 0; d < 36; d++) {
            float va = aA[d], vb = aB[d];
#pragma unroll
            for (int k = 0; k < 4; k++) {
                float wv = sm[RC_W1 + d * 144 + lane + 32 * k];
                fA[k] = fmaf(va, wv, fA[k]);
                fB[k] = fmaf(vb, wv, fB[k]);
            }
        }
#pragma unroll
        for (int k = 0; k < 4; k++) {
            gbA[lane + 32 * k] = gelu(fA[k]);
            gbB[lane + 32 * k] = gelu(fB[k]);
        }
        if (lane < 16) {
            float f4A = sm[RC_B1 + lane + 128], f4B = f4A;
#pragma unroll
            for (int d = 0; d < 36; d++) {
                float wv = sm[RC_W1 + d * 144 + lane + 128];
                f4A = fmaf(aA[d], wv, f4A);
                f4B = fmaf(aB[d], wv, f4B);
            }
            gbA[lane + 128] = gelu(f4A);
            gbB[lane + 128] = gelu(f4B);
        }
    }
    __syncwarp();

    // ---- FFN2 + residual ----
    float znA0, znB0, znA1 = 0.f, znB1 = 0.f;
    {
        float oA0 = sm[RC_B2 + j], oB0 = oA0;
        float oA1 = 0.f, oB1 = 0.f;
        if (e2) { oA1 = sm[RC_B2 + j2]; oB1 = oA1; }
#pragma unroll 4
        for (int d = 0; d < 144; d++) {
            float ga = gbA[d], gb = gbB[d];
            float wv = sm[RC_W2 + d * 36 + j];
            oA0 = fmaf(ga, wv, oA0);
            oB0 = fmaf(gb, wv, oB0);
            if (e2) {
                float wv2 = sm[RC_W2 + d * 36 + j2];
                oA1 = fmaf(ga, wv2, oA1);
                oB1 = fmaf(gb, wv2, oB1);
            }
        }
        znA0 = oA0 + tA0; znB0 = oB0 + tB0;
        znA1 = oA1 + tA1; znB1 = oB1 + tB1;
    }
    g_z[gA * 36 + j] = znA0;
    g_z[gB * 36 + j] = znB0;
    if (e2) { g_z[gA * 36 + j2] = znA1; g_z[gB * 36 + j2] = znB1; }

    if (Ln < 0) return;

    // ---- LN1 (next layer) ----
    {
        float sA = wred(znA0 + (e2 ? znA1 : 0.f));
        float qA = wred(znA0 * znA0 + (e2 ? znA1 * znA1 : 0.f));
        float sB = wred(znB0 + (e2 ? znB1 : 0.f));
        float qB = wred(znB0 * znB0 + (e2 ? znB1 * znB1 : 0.f));
        float mA = sA * (1.f / 36.f), mB = sB * (1.f / 36.f);
        float rsA = rsqrtf(qA * (1.f / 36.f) - mA * mA + 1e-6f);
        float rsB = rsqrtf(qB * (1.f / 36.f) - mB * mB + 1e-6f);
        bufA[j] = sm[RC_L1G + j] * (znA0 - mA) * rsA + sm[RC_L1B + j];
        bufB[j] = sm[RC_L1G + j] * (znB0 - mB) * rsB + sm[RC_L1B + j];
        if (e2) {
            bufA[j2] = sm[RC_L1G + j2] * (znA1 - mA) * rsA + sm[RC_L1B + j2];
            bufB[j2] = sm[RC_L1G + j2] * (znB1 - mB) * rsB + sm[RC_L1B + j2];
        }
    }
    __syncwarp();
#pragma unroll
    for (int d = 0; d < 36; d++) { aA[d] = bufA[d]; aB[d] = bufB[d]; }

    // ---- QKV (next layer) ----
    const int WOFF[3] = {RC_WQ, RC_WK, RC_WV};
    const int BOFF[3] = {RC_BQ, RC_BK, RC_BV};
    float* OUT[3] = {g_q, g_k, g_v};
#pragma unroll
    for (int m = 0; m < 3; m++) {
        const float* Ws = sm + WOFF[m];
        const float* bs = sm + BOFF[m];
        float cA0 = bs[j], cB0 = bs[j];
        float cA1 = 0.f, cB1 = 0.f;
        if (e2) { cA1 = bs[j2]; cB1 = bs[j2]; }
#pragma unroll
        for (int d = 0; d < 36; d++) {
            float wv = Ws[d * 36 + j];
            cA0 = fmaf(aA[d], wv, cA0);
            cB0 = fmaf(aB[d], wv, cB0);
            if (e2) {
                float wv2 = Ws[d * 36 + j2];
                cA1 = fmaf(aA[d], wv2, cA1);
                cB1 = fmaf(aB[d], wv2, cB1);
            }
        }
        OUT[m][gA * 36 + j] = cA0;
        OUT[m][gB * 36 + j] = cB0;
        if (e2) { OUT[m][gA * 36 + j2] = cA1; OUT[m][gB * 36 + j2] = cB1; }
    }
}

// ---------------- attention (unchanged from passing R5) ----------------
template<int DK, int NQ>
__device__ __forceinline__ void attn_head_group(
    const float* __restrict__ ksh, const float* __restrict__ vsh,
    const float* __restrict__ qsh, float* __restrict__ ob,
    int q0, int g, int off, int lane)
{
    float qreg[NQ][DK];
#pragma unroll
    for (int qq = 0; qq < NQ; qq++) {
        int ql = g * NQ + qq;
#pragma unroll
        for (int d = 0; d < DK; d++)
            qreg[qq][d] = (ql < QT) ? qsh[ql * 36 + off + d] : 0.f;
    }
    float sc[NQ][NI];
#pragma unroll
    for (int qq = 0; qq < NQ; qq++)
#pragma unroll
        for (int i = 0; i < NI; i++) sc[qq][i] = 0.f;

#pragma unroll
    for (int i = 0; i < NI; i++) {
        int m = i * 32 + lane;
        if (m < LSEQ) {
            const float* kr = ksh + m * 36 + off;
#pragma unroll
            for (int d = 0; d < DK; d++) {
                float kv = kr[d];
#pragma unroll
                for (int qq = 0; qq < NQ; qq++)
                    sc[qq][i] = fmaf(qreg[qq][d], kv, sc[qq][i]);
            }
        } else {
#pragma unroll
            for (int qq = 0; qq < NQ; qq++) sc[qq][i] = -1e30f;
        }
    }
    const float scale = rsqrtf((float)DK);
    float inv[NQ];
#pragma unroll
    for (int qq = 0; qq < NQ; qq++) {
        float mx = -1e30f;
#pragma unroll
        for (int i = 0; i < NI; i++) { float v = sc[qq][i] * scale; sc[qq][i] = v; mx = fmaxf(mx, v); }
#pragma unroll
        for (int o = 16; o > 0; o >>= 1) mx = fmaxf(mx, __shfl_xor_sync(0xffffffffu, mx, o));
        float smv = 0.f;
#pragma unroll
        for (int i = 0; i < NI; i++) { float p = __expf(sc[qq][i] - mx); sc[qq][i] = p; smv += p; }
#pragma unroll
        for (int o = 16; o > 0; o >>= 1) smv += __shfl_xor_sync(0xffffffffu, smv, o);
        inv[qq] = 1.f / smv;
    }
    float acc[NQ][DK];
#pragma unroll
    for (int qq = 0; qq < NQ; qq++)
#pragma unroll
        for (int d = 0; d < DK; d++) acc[qq][d] = 0.f;

#pragma unroll
    for (int i = 0; i < NI; i++) {
        int m = i * 32 + lane;
        if (m < LSEQ) {
            const float* vr = vsh + m * 36 + off;
#pragma unroll
            for (int d = 0; d < DK; d++) {
                float vv = vr[d];
#pragma unroll
                for (int qq = 0; qq < NQ; qq++)
                    acc[qq][d] = fmaf(sc[qq][i], vv, acc[qq][d]);
            }
        }
    }
#pragma unroll
    for (int qq = 0; qq < NQ; qq++) {
        int ql = g * NQ + qq;
#pragma unroll
        for (int d = 0; d < DK; d++) {
            float a = acc[qq][d];
#pragma unroll
            for (int o = 16; o > 0; o >>= 1) a += __shfl_xor_sync(0xffffffffu, a, o);
            if (ql < QT && lane == ((qq * DK + d) & 31))
                ob[(q0 + ql) * 36 + off + d] = a * inv[qq];
        }
    }
}

template<int DK, int NQ>
__device__ void attn_run(const float* ksh, const float* vsh, const float* qsh,
                         float* ob, int q0, int lane, int wid)
{
    constexpr int H  = 36 / DK;
    constexpr int NG = (QT + NQ - 1) / NQ;
    for (int hh = 0; hh < H; hh++) {
        int off = hh * DK;
        for (int g = wid; g < NG; g += 8)
            attn_head_group<DK, NQ>(ksh, vsh, qsh, ob, q0, g, off, lane);
    }
}

__global__ void __launch_bounds__(256, 1) attn_kernel(int4 heads4)
{
    extern __shared__ float sh[];
    float* ksh = sh;
    float* vsh = sh + 21600;
    float* qsh = sh + 43200;
    int tile = blockIdx.x, b = blockIdx.y, s = blockIdx.z;
    int h = pick4(heads4, s);
    int base = (s * 4 + b) * 21600;

    const float4* kg = (const float4*)(g_k + base);
    const float4* vg = (const float4*)(g_v + base);
    float4* k4 = (float4*)ksh;
    float4* v4 = (float4*)vsh;
    for (int i = threadIdx.x; i < 5400; i += 256) { k4[i] = kg[i]; v4[i] = vg[i]; }
    int q0 = tile * QT;
    for (int i = threadIdx.x; i < QT * 36; i += 256) qsh[i] = g_q[base + q0 * 36 + i];
    __syncthreads();

    int lane = threadIdx.x & 31, wid = threadIdx.x >> 5;
    float* ob = g_o + base;
    switch (h) {
        case 1:  attn_run<36, 2>(ksh, vsh, qsh, ob, q0, lane, wid); break;
        case 2:  attn_run<18, 2>(ksh, vsh, qsh, ob, q0, lane, wid); break;
        case 3:  attn_run<12, 3>(ksh, vsh, qsh, ob, q0, lane, wid); break;
        case 4:  attn_run<9,  4>(ksh, vsh, qsh, ob, q0, lane, wid); break;
        case 6:  attn_run<6,  4>(ksh, vsh, qsh, ob, q0, lane, wid); break;
        case 9:  attn_run<4,  4>(ksh, vsh, qsh, ob, q0, lane, wid); break;
        case 12: attn_run<3,  4>(ksh, vsh, qsh, ob, q0, lane, wid); break;
        case 18: attn_run<2,  4>(ksh, vsh, qsh, ob, q0, lane, wid); break;
        case 36: attn_run<1,  4>(ksh, vsh, qsh, ob, q0, lane, wid); break;
    }
}

// ---------------- SE gate ----------------
__global__ void __launch_bounds__(288) gate_kernel()
{
    int sb = blockIdx.x;
    __shared__ float red[288];
    int t = threadIdx.x;
    int c = t / 8, k = t % 8;
    float sum = 0.f;
    const float* zz = g_z + sb * 21600;
    for (int l = k; l < 600; l += 8) sum += zz[l * 36 + c];
    red[t] = sum;
    __syncthreads();
    if (k == 0) {
        float tot = 0.f;
#pragma unroll
        for (int i = 0; i < 8; i++) tot += red[c * 8 + i];
        float mean = tot * (1.f / 600.f);
        g_gate[sb * 36 + c] = 1.f / (1.f + __expf(-mean));
    }
}

// ---------------- conv + BN + ReLU ----------------
__global__ void __launch_bounds__(360) conv_kernel(
    const float* __restrict__ conv_w, const float* __restrict__ conv_b,
    const float* __restrict__ bn_g, const float* __restrict__ bn_b,
    const float* __restrict__ bn_mean, const float* __restrict__ bn_var,
    float* __restrict__ out)
{
    extern __shared__ float esh[];
    float* xf  = esh;
    float* wsh = esh + 144 * 32;
    int b = blockIdx.y, lbase = blockIdx.x * 30;
    int t = threadIdx.x;

    for (int idx = t; idx < 144 * 32; idx += 360) {
        int i = idx >> 5, lc = idx & 31;
        int l = lbase + lc - 1;
        float val = 0.f;
        if (l >= 0 && l < 600) {
            int s = i / 36, c = i % 36;
            val = g_gate[(s * 4 + b) * 36 + c] * g_z[((s * 4 + b) * 600 + l) * 36 + c];
        }
        xf[i * 32 + lc] = val;
    }
    for (int idx = t; idx < 36 * 432; idx += 360) {
        int o = idx / 432, rest = idx % 432;
        wsh[o * 433 + rest] = conv_w[idx];
    }
    __syncthreads();

    int o = t % 36, lj = t / 36;
    float scale = bn_g[o] * rsqrtf(bn_var[o] + 1e-5f);
    float shift = bn_b[o] - scale * bn_mean[o];
    float cb = conv_b[o];
    const float* w = wsh + o * 433;
#pragma unroll
    for (int rep = 0; rep < 3; rep++) {
        int lc = lj + rep * 10;
        float acc = cb;
#pragma unroll 8
        for (int i = 0; i < 144; i++) {
            float x0 = xf[i * 32 + lc];
            float x1 = xf[i * 32 + lc + 1];
            float x2 = xf[i * 32 + lc + 2];
            acc += x0 * w[i * 3 + 0] + x1 * w[i * 3 + 1] + x2 * w[i * 3 + 2];
        }
        float y = scale * acc + shift;
        out[b * 21600 + o * 600 + lbase + lc] = fmaxf(y, 0.f);
    }
}

// ---------------- host driver ----------------
extern "C" void kernel_launch(void* const* d_in, const int* in_sizes, int n_in,
                              void* d_out, int out_size)
{
    (void)in_sizes; (void)n_in; (void)out_size;
    const float* x     = (const float*)d_in[0];
    const float* ln1_g = (const float*)d_in[1];
    const float* ln1_b = (const float*)d_in[2];
    const float* Wq    = (const float*)d_in[3];
    const float* bq    = (const float*)d_in[4];
    const float* Wk    = (const float*)d_in[5];
    const float* bk    = (const float*)d_in[6];
    const float* Wv    = (const float*)d_in[7];
    const float* bv    = (const float*)d_in[8];
    const float* Wo    = (const float*)d_in[9];
    const float* bo    = (const float*)d_in[10];
    const float* ln2_g = (const float*)d_in[11];
    const float* ln2_b = (const float*)d_in[12];
    const float* W1    = (const float*)d_in[13];
    const float* b1    = (const float*)d_in[14];
    const float* W2    = (const float*)d_in[15];
    const float* b2    = (const float*)d_in[16];
    const float* conv_w = (const float*)d_in[17];
    const float* conv_b = (const float*)d_in[18];
    const float* bn_g   = (const float*)d_in[19];
    const float* bn_b   = (const float*)d_in[20];
    const float* bn_mean = (const float*)d_in[21];
    const float* bn_var  = (const float*)d_in[22];
    float* out = (float*)d_out;

    static const int HEADS_H[24] = {1,2,3,4,6,9,12,18,36,
                                    1,2,3,4,6,
                                    6,9,12,18,36,
                                    3,4,6,9,12};
    static const int START[4] = {0, 9, 14, 19};
    static const int DEPTH[4] = {9, 5, 5, 5};

    const int ATTN_SMEM = (21600 * 2 + QT * 36) * 4;
    const int CONV_SMEM = (144 * 32 + 36 * 433) * 4;
    const int RC_SMEM   = RC_TOT * 4;
    const int LQ_SMEM   = LQ_TOT * 4;
    cudaFuncSetAttribute(attn_kernel, cudaFuncAttributeMaxDynamicSharedMemorySize, ATTN_SMEM);
    cudaFuncSetAttribute(conv_kernel, cudaFuncAttributeMaxDynamicSharedMemorySize, CONV_SMEM);
    cudaFuncSetAttribute(rowchain_kernel, cudaFuncAttributeMaxDynamicSharedMemorySize, RC_SMEM);

    embed_kernel<<<1350, 256>>>(x);

    int4 L0 = make_int4(0, 9, 14, 19);
    lnqkv2_kernel<<<dim3(150, 1, 4), 256, LQ_SMEM>>>(L0, ln1_g, ln1_b,
                                                     Wq, bq, Wk, bk, Wv, bv);

    for (int t = 0; t < 9; t++) {
        int nA = (t < 5) ? 4 : 1;
        int lc[4], nx[4], hh[4];
        for (int s = 0; s < 4; s++) {
            int L = START[s] + t;
            lc[s] = (L < 24) ? L : 0;
            hh[s] = (t < DEPTH[s]) ? HEADS_H[lc[s]] : 1;
            nx[s] = (t + 1 < DEPTH[s]) ? lc[s] + 1 : -1;
        }
        int4 Lc = make_int4(lc[0], lc[1], lc[2], lc[3]);
        int4 Nx = make_int4(nx[0], nx[1], nx[2], nx[3]);
        int4 Hh = make_int4(hh[0], hh[1], hh[2], hh[3]);

        attn_kernel<<<dim3(NTILES, 4, nA), 256, ATTN_SMEM>>>(Hh);
        rowchain_kernel<<<dim3(150, 1, nA), 256, RC_SMEM>>>(
            Lc, Nx, Wo, bo, ln2_g, ln2_b, W1, b1, W2, b2,
            ln1_g, ln1_b, Wq, bq, Wk, bk, Wv, bv);
    }

    gate_kernel<<<16, 288>>>();
    conv_kernel<<<dim3(20, 4), 360, CONV_SMEM>>>(conv_w, conv_b, bn_g, bn_b,
                                                 bn_mean, bn_var, out);
}

// round 8
// speedup vs baseline: 1.7829x; 1.5721x over previous
#include <cuda_runtime.h>
#include <math.h>

#define NSTACK 4
#define BATCH  4
#define LSEQ   600
#define DMODEL 36
#define DFF    144
#define QT     30
#define NTILES 20
#define NI     19
#define KVP    37   // padded K/V row stride in smem (conflict-free)

// ---------------- scratch ----------------
__device__ float g_z[NSTACK*BATCH*LSEQ*DMODEL];
__device__ float g_q[NSTACK*BATCH*LSEQ*DMODEL];
__device__ float g_k[NSTACK*BATCH*LSEQ*DMODEL];
__device__ float g_v[NSTACK*BATCH*LSEQ*DMODEL];
__device__ float g_o[NSTACK*BATCH*LSEQ*DMODEL];
__device__ float g_gate[NSTACK*BATCH*DMODEL];

__device__ __forceinline__ int pick4(int4 v, int s) {
    return (s == 0) ? v.x : (s == 1) ? v.y : (s == 2) ? v.z : v.w;
}
__device__ __forceinline__ float wred(float v) {
#pragma unroll
    for (int o = 16; o > 0; o >>= 1) v += __shfl_xor_sync(0xffffffffu, v, o);
    return v;
}
// gelu(tanh approx) = u * sigmoid(2 * 0.79788456*(u + 0.044715 u^3))
__device__ __forceinline__ float gelu(float u) {
    float a = 1.5957691216057308f * (u + 0.044715f * u * u * u);
    return __fdividef(u, 1.f + __expf(-a));
}
__device__ __forceinline__ void cp4(float* dst, const float* __restrict__ src,
                                    int n, int tid, int nt) {
    const float4* s4 = (const float4*)src;
    float4* d4 = (float4*)dst;
    for (int i = tid; i < (n >> 2); i += nt) d4[i] = s4[i];
}

// ---------------- embedding ----------------
__global__ void embed_kernel(const float* __restrict__ x)
{
    int idx = blockIdx.x * blockDim.x + threadIdx.x;
    if (idx >= NSTACK * BATCH * LSEQ * DMODEL) return;
    int d = idx % 36;
    int l = (idx / 36) % 600;
    int b = (idx / 21600) % 4;
    int j = d >> 1;
    float freq = __expf(-logf(10000.f) * (float)(2 * j) / 36.f);
    float ang = (float)l * freq;
    float pe = (d & 1) ? cosf(ang) : sinf(ang);
    g_z[idx] = x[b * 21600 + d * 600 + l] + pe;
}

// =============================================================
// Initial LN1 + QKV: 512 threads, 16 warps, 2 rows/warp
// =============================================================
#define LQ_WQ 0
#define LQ_WK 1296
#define LQ_WV 2592
#define LQ_LG 3888
#define LQ_LB 3924
#define LQ_BQ 3960
#define LQ_BK 3996
#define LQ_BV 4032
#define LQ_YB 4068
#define LQ_TOT (4068 + 32*40)

__global__ void __launch_bounds__(512, 1) lnqkv2_kernel(
    int4 layer4,
    const float* __restrict__ ln1_g, const float* __restrict__ ln1_b,
    const float* __restrict__ Wq, const float* __restrict__ bq,
    const float* __restrict__ Wk, const float* __restrict__ bk,
    const float* __restrict__ Wv, const float* __restrict__ bv)
{
    extern __shared__ float sm[];
    int tid = threadIdx.x, lane = tid & 31, w = tid >> 5;
    int s = blockIdx.z;
    int L = pick4(layer4, s);

    cp4(sm + LQ_WQ, Wq + L * 1296, 1296, tid, 512);
    cp4(sm + LQ_WK, Wk + L * 1296, 1296, tid, 512);
    cp4(sm + LQ_WV, Wv + L * 1296, 1296, tid, 512);
    cp4(sm + LQ_LG, ln1_g + L * 36, 36, tid, 512);
    cp4(sm + LQ_LB, ln1_b + L * 36, 36, tid, 512);
    cp4(sm + LQ_BQ, bq + L * 36, 36, tid, 512);
    cp4(sm + LQ_BK, bk + L * 36, 36, tid, 512);
    cp4(sm + LQ_BV, bv + L * 36, 36, tid, 512);
    __syncthreads();

    int rA = blockIdx.x * 32 + w * 2;
    int gA = s * 2400 + rA, gB = gA + 1;
    int j = lane, j2 = lane + 32;
    bool e2 = lane < 4;
    float* bufA = sm + LQ_YB + (w * 2) * 40;
    float* bufB = bufA + 40;

    bufA[lane] = g_z[gA * 36 + lane];
    bufB[lane] = g_z[gB * 36 + lane];
    if (e2) { bufA[j2] = g_z[gA * 36 + j2]; bufB[j2] = g_z[gB * 36 + j2]; }
    __syncwarp();

    float tA0 = bufA[j], tB0 = bufB[j];
    float tA1 = e2 ? bufA[j2] : 0.f, tB1 = e2 ? bufB[j2] : 0.f;
    float sA = wred(tA0 + (e2 ? tA1 : 0.f));
    float qA = wred(tA0 * tA0 + (e2 ? tA1 * tA1 : 0.f));
    float sB = wred(tB0 + (e2 ? tB1 : 0.f));
    float qB = wred(tB0 * tB0 + (e2 ? tB1 * tB1 : 0.f));
    float mA = sA * (1.f / 36.f), mB = sB * (1.f / 36.f);
    float rsA = rsqrtf(qA * (1.f / 36.f) - mA * mA + 1e-6f);
    float rsB = rsqrtf(qB * (1.f / 36.f) - mB * mB + 1e-6f);

    bufA[j] = sm[LQ_LG + j] * (tA0 - mA) * rsA + sm[LQ_LB + j];
    bufB[j] = sm[LQ_LG + j] * (tB0 - mB) * rsB + sm[LQ_LB + j];
    if (e2) {
        bufA[j2] = sm[LQ_LG + j2] * (tA1 - mA) * rsA + sm[LQ_LB + j2];
        bufB[j2] = sm[LQ_LG + j2] * (tB1 - mB) * rsB + sm[LQ_LB + j2];
    }
    __syncwarp();

    float aA[36], aB[36];
#pragma unroll
    for (int d = 0; d < 36; d++) { aA[d] = bufA[d]; aB[d] = bufB[d]; }

    const int WOFF[3] = {LQ_WQ, LQ_WK, LQ_WV};
    const int BOFF[3] = {LQ_BQ, LQ_BK, LQ_BV};
    float* OUT[3] = {g_q, g_k, g_v};
#pragma unroll
    for (int m = 0; m < 3; m++) {
        const float* Ws = sm + WOFF[m];
        const float* bs = sm + BOFF[m];
        float cA0 = bs[j], cB0 = bs[j];
        float cA1 = 0.f, cB1 = 0.f;
        if (e2) { cA1 = bs[j2]; cB1 = bs[j2]; }
#pragma unroll
        for (int d = 0; d < 36; d++) {
            float wv = Ws[d * 36 + j];
            cA0 = fmaf(aA[d], wv, cA0);
            cB0 = fmaf(aB[d], wv, cB0);
            if (e2) {
                float wv2 = Ws[d * 36 + j2];
                cA1 = fmaf(aA[d], wv2, cA1);
                cB1 = fmaf(aB[d], wv2, cB1);
            }
        }
        OUT[m][gA * 36 + j] = cA0;
        OUT[m][gB * 36 + j] = cB0;
        if (e2) { OUT[m][gA * 36 + j2] = cA1; OUT[m][gB * 36 + j2] = cB1; }
    }
}

// =============================================================
// Fused row chain, 512 threads = 16 warps = 32 rows
// =============================================================
#define RC_WO   0
#define RC_W1   1296
#define RC_W2   6480
#define RC_WQ   11664
#define RC_WK   12960
#define RC_WV   14256
#define RC_BO   15552
#define RC_L2G  15588
#define RC_L2B  15624
#define RC_B2   15660
#define RC_B1   15696
#define RC_L1G  15840
#define RC_L1B  15876
#define RC_BQ   15912
#define RC_BK   15948
#define RC_BV   15984
#define RC_YB   16020
#define RC_GB   (16020 + 32*40)
#define RC_TOT  (RC_GB + 32*144)

__global__ void __launch_bounds__(512, 1) rowchain_kernel(
    int4 layer4, int4 next4,
    const float* __restrict__ Wo, const float* __restrict__ bo,
    const float* __restrict__ ln2_g, const float* __restrict__ ln2_b,
    const float* __restrict__ W1, const float* __restrict__ b1,
    const float* __restrict__ W2, const float* __restrict__ b2,
    const float* __restrict__ ln1_g, const float* __restrict__ ln1_b,
    const float* __restrict__ Wq, const float* __restrict__ bq,
    const float* __restrict__ Wk, const float* __restrict__ bk,
    const float* __restrict__ Wv, const float* __restrict__ bv)
{
    extern __shared__ float sm[];
    int tid = threadIdx.x, lane = tid & 31, w = tid >> 5;
    int s = blockIdx.z;
    int L = pick4(layer4, s);
    int Ln = pick4(next4, s);

    cp4(sm + RC_WO, Wo + L * 1296, 1296, tid, 512);
    cp4(sm + RC_W1, W1 + L * 5184, 5184, tid, 512);
    cp4(sm + RC_W2, W2 + L * 5184, 5184, tid, 512);
    cp4(sm + RC_BO, bo + L * 36, 36, tid, 512);
    cp4(sm + RC_L2G, ln2_g + L * 36, 36, tid, 512);
    cp4(sm + RC_L2B, ln2_b + L * 36, 36, tid, 512);
    cp4(sm + RC_B2, b2 + L * 36, 36, tid, 512);
    cp4(sm + RC_B1, b1 + L * 144, 144, tid, 512);
    if (Ln >= 0) {
        cp4(sm + RC_WQ, Wq + Ln * 1296, 1296, tid, 512);
        cp4(sm + RC_WK, Wk + Ln * 1296, 1296, tid, 512);
        cp4(sm + RC_WV, Wv + Ln * 1296, 1296, tid, 512);
        cp4(sm + RC_L1G, ln1_g + Ln * 36, 36, tid, 512);
        cp4(sm + RC_L1B, ln1_b + Ln * 36, 36, tid, 512);
        cp4(sm + RC_BQ, bq + Ln * 36, 36, tid, 512);
        cp4(sm + RC_BK, bk + Ln * 36, 36, tid, 512);
        cp4(sm + RC_BV, bv + Ln * 36, 36, tid, 512);
    }
    __syncthreads();

    int rA = blockIdx.x * 32 + w * 2;
    int gA = s * 2400 + rA, gB = gA + 1;
    int j = lane, j2 = lane + 32;
    bool e2 = lane < 4;
    float* bufA = sm + RC_YB + (w * 2) * 40;
    float* bufB = bufA + 40;
    float* gbA  = sm + RC_GB + (w * 2) * 144;
    float* gbB  = gbA + 144;

    bufA[lane] = g_o[gA * 36 + lane];
    bufB[lane] = g_o[gB * 36 + lane];
    if (e2) { bufA[j2] = g_o[gA * 36 + j2]; bufB[j2] = g_o[gB * 36 + j2]; }
    __syncwarp();

    float aA[36], aB[36];
#pragma unroll
    for (int d = 0; d < 36; d++) { aA[d] = bufA[d]; aB[d] = bufB[d]; }

    float zA0 = g_z[gA * 36 + j], zB0 = g_z[gB * 36 + j];
    float zA1 = e2 ? g_z[gA * 36 + j2] : 0.f;
    float zB1 = e2 ? g_z[gB * 36 + j2] : 0.f;

    // ---- o-projection + residual ----
    float tA0 = sm[RC_BO + j], tB0 = sm[RC_BO + j];
    float tA1 = 0.f, tB1 = 0.f;
    if (e2) { tA1 = sm[RC_BO + j2]; tB1 = sm[RC_BO + j2]; }
#pragma unroll
    for (int d = 0; d < 36; d++) {
        float wv = sm[RC_WO + d * 36 + j];
        tA0 = fmaf(aA[d], wv, tA0);
        tB0 = fmaf(aB[d], wv, tB0);
        if (e2) {
            float wv2 = sm[RC_WO + d * 36 + j2];
            tA1 = fmaf(aA[d], wv2, tA1);
            tB1 = fmaf(aB[d], wv2, tB1);
        }
    }
    tA0 += zA0; tB0 += zB0; tA1 += zA1; tB1 += zB1;

    // ---- LN2 ----
    {
        float sA = wred(tA0 + (e2 ? tA1 : 0.f));
        float qA = wred(tA0 * tA0 + (e2 ? tA1 * tA1 : 0.f));
        float sB = wred(tB0 + (e2 ? tB1 : 0.f));
        float qB = wred(tB0 * tB0 + (e2 ? tB1 * tB1 : 0.f));
        float mA = sA * (1.f / 36.f), mB = sB * (1.f / 36.f);
        float rsA = rsqrtf(qA * (1.f / 36.f) - mA * mA + 1e-6f);
        float rsB = rsqrtf(qB * (1.f / 36.f) - mB * mB + 1e-6f);
        bufA[j] = sm[RC_L2G + j] * (tA0 - mA) * rsA + sm[RC_L2B + j];
        bufB[j] = sm[RC_L2G + j] * (tB0 - mB) * rsB + sm[RC_L2B + j];
        if (e2) {
            bufA[j2] = sm[RC_L2G + j2] * (tA1 - mA) * rsA + sm[RC_L2B + j2];
            bufB[j2] = sm[RC_L2G + j2] * (tB1 - mB) * rsB + sm[RC_L2B + j2];
        }
    }
    __syncwarp();
#pragma unroll
    for (int d = 0; d < 36; d++) { aA[d] = bufA[d]; aB[d] = bufB[d]; }

    // ---- FFN1 + GELU ----
    {
        float fA[4], fB[4];
#pragma unroll
        for (int k = 0; k < 4; k++) {
            fA[k] = sm[RC_B1 + lane + 32 * k];
            fB[k] = fA[k];
        }
#pragma unroll
        for (int d = 0; d < 36; d++) {
            float va = aA[d], vb = aB[d];
#pragma unroll
            for (int k = 0; k < 4; k++) {
                float wv = sm[RC_W1 + d * 144 + lane + 32 * k];
                fA[k] = fmaf(va, wv, fA[k]);
                fB[k] = fmaf(vb, wv, fB[k]);
            }
        }
#pragma unroll
        for (int k = 0; k < 4; k++) {
            gbA[lane + 32 * k] = gelu(fA[k]);
            gbB[lane + 32 * k] = gelu(fB[k]);
        }
        if (lane < 16) {
            float f4A = sm[RC_B1 + lane + 128], f4B = f4A;
#pragma unroll
            for (int d = 0; d < 36; d++) {
                float wv = sm[RC_W1 + d * 144 + lane + 128];
                f4A = fmaf(aA[d], wv, f4A);
                f4B = fmaf(aB[d], wv, f4B);
            }
            gbA[lane + 128] = gelu(f4A);
            gbB[lane + 128] = gelu(f4B);
        }
    }
    __syncwarp();

    // ---- FFN2 + residual ----
    float znA0, znB0, znA1 = 0.f, znB1 = 0.f;
    {
        float oA0 = sm[RC_B2 + j], oB0 = oA0;
        float oA1 = 0.f, oB1 = 0.f;
        if (e2) { oA1 = sm[RC_B2 + j2]; oB1 = oA1; }
#pragma unroll 4
        for (int d = 0; d < 144; d++) {
            float ga = gbA[d], gb = gbB[d];
            float wv = sm[RC_W2 + d * 36 + j];
            oA0 = fmaf(ga, wv, oA0);
            oB0 = fmaf(gb, wv, oB0);
            if (e2) {
                float wv2 = sm[RC_W2 + d * 36 + j2];
                oA1 = fmaf(ga, wv2, oA1);
                oB1 = fmaf(gb, wv2, oB1);
            }
        }
        znA0 = oA0 + tA0; znB0 = oB0 + tB0;
        znA1 = oA1 + tA1; znB1 = oB1 + tB1;
    }
    g_z[gA * 36 + j] = znA0;
    g_z[gB * 36 + j] = znB0;
    if (e2) { g_z[gA * 36 + j2] = znA1; g_z[gB * 36 + j2] = znB1; }

    if (Ln < 0) return;

    // ---- LN1 (next) ----
    {
        float sA = wred(znA0 + (e2 ? znA1 : 0.f));
        float qA = wred(znA0 * znA0 + (e2 ? znA1 * znA1 : 0.f));
        float sB = wred(znB0 + (e2 ? znB1 : 0.f));
        float qB = wred(znB0 * znB0 + (e2 ? znB1 * znB1 : 0.f));
        float mA = sA * (1.f / 36.f), mB = sB * (1.f / 36.f);
        float rsA = rsqrtf(qA * (1.f / 36.f) - mA * mA + 1e-6f);
        float rsB = rsqrtf(qB * (1.f / 36.f) - mB * mB + 1e-6f);
        bufA[j] = sm[RC_L1G + j] * (znA0 - mA) * rsA + sm[RC_L1B + j];
        bufB[j] = sm[RC_L1G + j] * (znB0 - mB) * rsB + sm[RC_L1B + j];
        if (e2) {
            bufA[j2] = sm[RC_L1G + j2] * (znA1 - mA) * rsA + sm[RC_L1B + j2];
            bufB[j2] = sm[RC_L1G + j2] * (znB1 - mB) * rsB + sm[RC_L1B + j2];
        }
    }
    __syncwarp();
#pragma unroll
    for (int d = 0; d < 36; d++) { aA[d] = bufA[d]; aB[d] = bufB[d]; }

    // ---- QKV (next) ----
    const int WOFF[3] = {RC_WQ, RC_WK, RC_WV};
    const int BOFF[3] = {RC_BQ, RC_BK, RC_BV};
    float* OUT[3] = {g_q, g_k, g_v};
#pragma unroll
    for (int m = 0; m < 3; m++) {
        const float* Ws = sm + WOFF[m];
        const float* bs = sm + BOFF[m];
        float cA0 = bs[j], cB0 = bs[j];
        float cA1 = 0.f, cB1 = 0.f;
        if (e2) { cA1 = bs[j2]; cB1 = bs[j2]; }
#pragma unroll
        for (int d = 0; d < 36; d++) {
            float wv = Ws[d * 36 + j];
            cA0 = fmaf(aA[d], wv, cA0);
            cB0 = fmaf(aB[d], wv, cB0);
            if (e2) {
                float wv2 = Ws[d * 36 + j2];
                cA1 = fmaf(aA[d], wv2, cA1);
                cB1 = fmaf(aB[d], wv2, cB1);
            }
        }
        OUT[m][gA * 36 + j] = cA0;
        OUT[m][gB * 36 + j] = cB0;
        if (e2) { OUT[m][gA * 36 + j2] = cA1; OUT[m][gB * 36 + j2] = cB1; }
    }
}

// =============================================================
// attention: padded smem (no bank conflicts), single-pass
// online softmax (no score array, no max-subtract), 512 thr
// =============================================================
template<int DK, int NQ>
__device__ __forceinline__ void attn_head_group(
    const float* __restrict__ ksh, const float* __restrict__ vsh,
    const float* __restrict__ qsh, float* __restrict__ ob,
    int q0, int g, int off, int lane)
{
    float qreg[NQ][DK];
#pragma unroll
    for (int qq = 0; qq < NQ; qq++) {
        int ql = g * NQ + qq;
#pragma unroll
        for (int d = 0; d < DK; d++)
            qreg[qq][d] = (ql < QT) ? qsh[ql * 36 + off + d] : 0.f;
    }
    float acc[NQ][DK];
    float ssum[NQ];
#pragma unroll
    for (int qq = 0; qq < NQ; qq++) {
        ssum[qq] = 0.f;
#pragma unroll
        for (int d = 0; d < DK; d++) acc[qq][d] = 0.f;
    }
    const float scale = rsqrtf((float)DK);
    for (int i = 0; i < NI; i++) {
        int m = i * 32 + lane;
        if (m < LSEQ) {
            const float* kr = ksh + m * KVP + off;
            const float* vr = vsh + m * KVP + off;
            float p[NQ];
#pragma unroll
            for (int qq = 0; qq < NQ; qq++) p[qq] = 0.f;
#pragma unroll
            for (int d = 0; d < DK; d++) {
                float kv = kr[d];
#pragma unroll
                for (int qq = 0; qq < NQ; qq++)
                    p[qq] = fmaf(qreg[qq][d], kv, p[qq]);
            }
#pragma unroll
            for (int qq = 0; qq < NQ; qq++) {
                p[qq] = __expf(p[qq] * scale);
                ssum[qq] += p[qq];
            }
#pragma unroll
            for (int d = 0; d < DK; d++) {
                float vv = vr[d];
#pragma unroll
                for (int qq = 0; qq < NQ; qq++)
                    acc[qq][d] = fmaf(p[qq], vv, acc[qq][d]);
            }
        }
    }
    float inv[NQ];
#pragma unroll
    for (int qq = 0; qq < NQ; qq++) {
        float sv = wred(ssum[qq]);
        inv[qq] = 1.f / sv;
    }
#pragma unroll
    for (int qq = 0; qq < NQ; qq++) {
        int ql = g * NQ + qq;
#pragma unroll
        for (int d = 0; d < DK; d++) {
            float a = wred(acc[qq][d]);
            if (ql < QT && lane == ((qq * DK + d) & 31))
                ob[(q0 + ql) * 36 + off + d] = a * inv[qq];
        }
    }
}

template<int DK, int NQ>
__device__ void attn_run(const float* ksh, const float* vsh, const float* qsh,
                         float* ob, int q0, int lane, int wid)
{
    constexpr int H  = 36 / DK;
    constexpr int NG = (QT + NQ - 1) / NQ;
    for (int u = wid; u < H * NG; u += 16) {
        int hh = u / NG, g = u % NG;
        attn_head_group<DK, NQ>(ksh, vsh, qsh, ob, q0, g, hh * DK, lane);
    }
}

__global__ void __launch_bounds__(512, 1) attn_kernel(int4 heads4)
{
    extern __shared__ float sh[];
    float* ksh = sh;
    float* vsh = sh + 600 * KVP;
    float* qsh = sh + 1200 * KVP;
    int tile = blockIdx.x, b = blockIdx.y, s = blockIdx.z;
    int h = pick4(heads4, s);
    int base = (s * 4 + b) * 21600;

    const float4* kg = (const float4*)(g_k + base);
    const float4* vg = (const float4*)(g_v + base);
    for (int i4 = threadIdx.x; i4 < 5400; i4 += 512) {
        int row = i4 / 9, c = (i4 % 9) * 4;
        float4 kv = kg[i4], vv = vg[i4];
        float* kd = ksh + row * KVP + c;
        kd[0] = kv.x; kd[1] = kv.y; kd[2] = kv.z; kd[3] = kv.w;
        float* vd = vsh + row * KVP + c;
        vd[0] = vv.x; vd[1] = vv.y; vd[2] = vv.z; vd[3] = vv.w;
    }
    int q0 = tile * QT;
    for (int i = threadIdx.x; i < QT * 36; i += 512) qsh[i] = g_q[base + q0 * 36 + i];
    __syncthreads();

    int lane = threadIdx.x & 31, wid = threadIdx.x >> 5;
    float* ob = g_o + base;
    switch (h) {
        case 1:  attn_run<36, 1>(ksh, vsh, qsh, ob, q0, lane, wid); break;
        case 2:  attn_run<18, 2>(ksh, vsh, qsh, ob, q0, lane, wid); break;
        case 3:  attn_run<12, 3>(ksh, vsh, qsh, ob, q0, lane, wid); break;
        case 4:  attn_run<9,  4>(ksh, vsh, qsh, ob, q0, lane, wid); break;
        case 6:  attn_run<6,  6>(ksh, vsh, qsh, ob, q0, lane, wid); break;
        case 9:  attn_run<4,  6>(ksh, vsh, qsh, ob, q0, lane, wid); break;
        case 12: attn_run<3,  6>(ksh, vsh, qsh, ob, q0, lane, wid); break;
        case 18: attn_run<2,  6>(ksh, vsh, qsh, ob, q0, lane, wid); break;
        case 36: attn_run<1, 10>(ksh, vsh, qsh, ob, q0, lane, wid); break;
    }
}

// ---------------- SE gate ----------------
__global__ void __launch_bounds__(288) gate_kernel()
{
    int sb = blockIdx.x;
    __shared__ float red[288];
    int t = threadIdx.x;
    int c = t / 8, k = t % 8;
    float sum = 0.f;
    const float* zz = g_z + sb * 21600;
    for (int l = k; l < 600; l += 8) sum += zz[l * 36 + c];
    red[t] = sum;
    __syncthreads();
    if (k == 0) {
        float tot = 0.f;
#pragma unroll
        for (int i = 0; i < 8; i++) tot += red[c * 8 + i];
        float mean = tot * (1.f / 600.f);
        g_gate[sb * 36 + c] = 1.f / (1.f + __expf(-mean));
    }
}

// ---------------- conv + BN + ReLU ----------------
__global__ void __launch_bounds__(360) conv_kernel(
    const float* __restrict__ conv_w, const float* __restrict__ conv_b,
    const float* __restrict__ bn_g, const float* __restrict__ bn_b,
    const float* __restrict__ bn_mean, const float* __restrict__ bn_var,
    float* __restrict__ out)
{
    extern __shared__ float esh[];
    float* xf  = esh;
    float* wsh = esh + 144 * 32;
    int b = blockIdx.y, lbase = blockIdx.x * 30;
    int t = threadIdx.x;

    for (int idx = t; idx < 144 * 32; idx += 360) {
        int i = idx >> 5, lc = idx & 31;
        int l = lbase + lc - 1;
        float val = 0.f;
        if (l >= 0 && l < 600) {
            int s = i / 36, c = i % 36;
            val = g_gate[(s * 4 + b) * 36 + c] * g_z[((s * 4 + b) * 600 + l) * 36 + c];
        }
        xf[i * 32 + lc] = val;
    }
    for (int idx = t; idx < 36 * 432; idx += 360) {
        int o = idx / 432, rest = idx % 432;
        wsh[o * 433 + rest] = conv_w[idx];
    }
    __syncthreads();

    int o = t % 36, lj = t / 36;
    float scale = bn_g[o] * rsqrtf(bn_var[o] + 1e-5f);
    float shift = bn_b[o] - scale * bn_mean[o];
    float cb = conv_b[o];
    const float* w = wsh + o * 433;
#pragma unroll
    for (int rep = 0; rep < 3; rep++) {
        int lc = lj + rep * 10;
        float acc = cb;
#pragma unroll 8
        for (int i = 0; i < 144; i++) {
            float x0 = xf[i * 32 + lc];
            float x1 = xf[i * 32 + lc + 1];
            float x2 = xf[i * 32 + lc + 2];
            acc += x0 * w[i * 3 + 0] + x1 * w[i * 3 + 1] + x2 * w[i * 3 + 2];
        }
        float y = scale * acc + shift;
        out[b * 21600 + o * 600 + lbase + lc] = fmaxf(y, 0.f);
    }
}

// ---------------- host driver ----------------
extern "C" void kernel_launch(void* const* d_in, const int* in_sizes, int n_in,
                              void* d_out, int out_size)
{
    (void)in_sizes; (void)n_in; (void)out_size;
    const float* x     = (const float*)d_in[0];
    const float* ln1_g = (const float*)d_in[1];
    const float* ln1_b = (const float*)d_in[2];
    const float* Wq    = (const float*)d_in[3];
    const float* bq    = (const float*)d_in[4];
    const float* Wk    = (const float*)d_in[5];
    const float* bk    = (const float*)d_in[6];
    const float* Wv    = (const float*)d_in[7];
    const float* bv    = (const float*)d_in[8];
    const float* Wo    = (const float*)d_in[9];
    const float* bo    = (const float*)d_in[10];
    const float* ln2_g = (const float*)d_in[11];
    const float* ln2_b = (const float*)d_in[12];
    const float* W1    = (const float*)d_in[13];
    const float* b1    = (const float*)d_in[14];
    const float* W2    = (const float*)d_in[15];
    const float* b2    = (const float*)d_in[16];
    const float* conv_w = (const float*)d_in[17];
    const float* conv_b = (const float*)d_in[18];
    const float* bn_g   = (const float*)d_in[19];
    const float* bn_b   = (const float*)d_in[20];
    const float* bn_mean = (const float*)d_in[21];
    const float* bn_var  = (const float*)d_in[22];
    float* out = (float*)d_out;

    static const int HEADS_H[24] = {1,2,3,4,6,9,12,18,36,
                                    1,2,3,4,6,
                                    6,9,12,18,36,
                                    3,4,6,9,12};
    static const int START[4] = {0, 9, 14, 19};
    static const int DEPTH[4] = {9, 5, 5, 5};

    const int ATTN_SMEM = (1200 * KVP + QT * 36) * 4;   // 181920 B
    const int CONV_SMEM = (144 * 32 + 36 * 433) * 4;
    const int RC_SMEM   = RC_TOT * 4;
    const int LQ_SMEM   = LQ_TOT * 4;
    cudaFuncSetAttribute(attn_kernel, cudaFuncAttributeMaxDynamicSharedMemorySize, ATTN_SMEM);
    cudaFuncSetAttribute(conv_kernel, cudaFuncAttributeMaxDynamicSharedMemorySize, CONV_SMEM);
    cudaFuncSetAttribute(rowchain_kernel, cudaFuncAttributeMaxDynamicSharedMemorySize, RC_SMEM);
    cudaFuncSetAttribute(lnqkv2_kernel, cudaFuncAttributeMaxDynamicSharedMemorySize, LQ_SMEM);

    embed_kernel<<<1350, 256>>>(x);

    int4 L0 = make_int4(0, 9, 14, 19);
    lnqkv2_kernel<<<dim3(75, 1, 4), 512, LQ_SMEM>>>(L0, ln1_g, ln1_b,
                                                    Wq, bq, Wk, bk, Wv, bv);

    for (int t = 0; t < 9; t++) {
        int nA = (t < 5) ? 4 : 1;
        int lc[4], nx[4], hh[4];
        for (int s = 0; s < 4; s++) {
            int L = START[s] + t;
            lc[s] = (L < 24) ? L : 0;
            hh[s] = (t < DEPTH[s]) ? HEADS_H[lc[s]] : 1;
            nx[s] = (t + 1 < DEPTH[s]) ? lc[s] + 1 : -1;
        }
        int4 Lc = make_int4(lc[0], lc[1], lc[2], lc[3]);
        int4 Nx = make_int4(nx[0], nx[1], nx[2], nx[3]);
        int4 Hh = make_int4(hh[0], hh[1], hh[2], hh[3]);

        attn_kernel<<<dim3(NTILES, 4, nA), 512, ATTN_SMEM>>>(Hh);
        rowchain_kernel<<<dim3(75, 1, nA), 512, RC_SMEM>>>(
            Lc, Nx, Wo, bo, ln2_g, ln2_b, W1, b1, W2, b2,
            ln1_g, ln1_b, Wq, bq, Wk, bk, Wv, bv);
    }

    gate_kernel<<<16, 288>>>();
    conv_kernel<<<dim3(20, 4), 360, CONV_SMEM>>>(conv_w, conv_b, bn_g, bn_b,
                                                 bn_mean, bn_var, out);
}